// round 1
// baseline (speedup 1.0000x reference)
#include <cuda_runtime.h>
#include <cstdint>

// Problem constants
#define SEQ 2048
#define HID 4096
#define NH  32
#define NKV 8
#define HD  128
#define ROPE_D 64

// Scratch (device globals -> no allocations)
__device__ float g_q [(size_t)SEQ * NH  * HD];   // 32 MB
__device__ float g_k [(size_t)SEQ * NKV * HD];   // 8 MB
__device__ float g_v [(size_t)SEQ * NKV * HD];   // 8 MB
__device__ float g_sc[(size_t)NH * SEQ * SEQ];   // 512 MB
__device__ float g_at[(size_t)SEQ * NH  * HD];   // 32 MB

// ---------------------------------------------------------------------------
// Generic tiled SGEMM: C[M,N] = alpha * A[M,K] * op(B)
//   TRANSB=0: B is K x N (row-major)   TRANSB=1: B is N x K (row-major) -> B^T
// Batched over blockIdx.z with element strides sA/sB/sC; B batch index is
// z / zdivB (for GQA head sharing).
// CAUSAL && TRANSB : skip output tiles fully above the diagonal (bn > bm)
// CAUSAL && !TRANSB: limit K loop to (bm+1)*128 (A columns beyond are zero)
// Requires: M%128==0, N%128==0, K%8==0, lda/ldb%4==0.
// ---------------------------------------------------------------------------
template<int TRANSB, int CAUSAL>
__global__ __launch_bounds__(256)
void sgemm_kernel(const float* __restrict__ A, const float* __restrict__ B,
                  float* __restrict__ C, int M, int N, int K,
                  int lda, int ldb, int ldc,
                  long long sA, long long sB, long long sC, int zdivB,
                  float alpha)
{
    int bm = blockIdx.y, bn = blockIdx.x, bz = blockIdx.z;
    if (CAUSAL && TRANSB && bn > bm) return;

    A += (long long)bz * sA;
    B += (long long)(bz / zdivB) * sB;
    C += (long long)bz * sC;

    int Kend = K;
    if (CAUSAL && !TRANSB) {
        int lim = (bm + 1) * 128;
        Kend = (K < lim) ? K : lim;
    }

    __shared__ float As[8][128];
    __shared__ float Bs[8][128];

    int tid = threadIdx.x;
    int tx = tid & 15, ty = tid >> 4;

    float acc[8][8];
#pragma unroll
    for (int i = 0; i < 8; i++)
#pragma unroll
        for (int j = 0; j < 8; j++) acc[i][j] = 0.f;

    // A load mapping: 128 rows x 8 cols, one float4 per thread
    int arow = tid >> 1;
    int acol = (tid & 1) * 4;
    const float* Aptr = A + (long long)(bm * 128 + arow) * lda + acol;

    const float* Bptr;
    int brow, bcol;
    if (TRANSB) {
        brow = tid >> 1;            // 0..127 (n index)
        bcol = (tid & 1) * 4;       // k offset
        Bptr = B + (long long)(bn * 128 + brow) * ldb + bcol;
    } else {
        brow = tid >> 5;            // 0..7 (k index)
        bcol = (tid & 31) * 4;      // n offset
        Bptr = B + (long long)brow * ldb + bn * 128 + bcol;
    }

    for (int k0 = 0; k0 < Kend; k0 += 8) {
        float4 av = *(const float4*)(Aptr + k0);
        As[acol + 0][arow] = av.x;
        As[acol + 1][arow] = av.y;
        As[acol + 2][arow] = av.z;
        As[acol + 3][arow] = av.w;
        if (TRANSB) {
            float4 bv = *(const float4*)(Bptr + k0);
            Bs[bcol + 0][brow] = bv.x;
            Bs[bcol + 1][brow] = bv.y;
            Bs[bcol + 2][brow] = bv.z;
            Bs[bcol + 3][brow] = bv.w;
        } else {
            float4 bv = *(const float4*)(Bptr + (long long)k0 * ldb);
            *(float4*)&Bs[brow][bcol] = bv;
        }
        __syncthreads();

#pragma unroll
        for (int kk = 0; kk < 8; kk++) {
            float a[8], b[8];
#pragma unroll
            for (int i = 0; i < 8; i++) a[i] = As[kk][ty * 8 + i];
#pragma unroll
            for (int j = 0; j < 8; j++) b[j] = Bs[kk][tx * 8 + j];
#pragma unroll
            for (int i = 0; i < 8; i++)
#pragma unroll
                for (int j = 0; j < 8; j++) acc[i][j] += a[i] * b[j];
        }
        __syncthreads();
    }

#pragma unroll
    for (int i = 0; i < 8; i++) {
        long long row = bm * 128 + ty * 8 + i;
#pragma unroll
        for (int j = 0; j < 8; j++) {
            C[row * ldc + bn * 128 + tx * 8 + j] = alpha * acc[i][j];
        }
    }
}

// ---------------------------------------------------------------------------
// RoPE on Q (32 heads) and K (8 heads), first 64 dims of each head.
// rotate_half on the 64-dim slice: rh[d] = -x[d+32] (d<32), x[d-32] (d>=32)
// out = x*cos + rh*sin
// One thread per (s, head, pair p<32). heads 0..31 -> Q, 32..39 -> K.
// ---------------------------------------------------------------------------
__global__ void rope_kernel(float* __restrict__ q, float* __restrict__ k,
                            const float* __restrict__ cosb,
                            const float* __restrict__ sinb)
{
    int idx = blockIdx.x * blockDim.x + threadIdx.x;
    const int total = SEQ * (NH + NKV) * (ROPE_D / 2);
    if (idx >= total) return;
    int p = idx & 31;
    int rest = idx >> 5;
    int head = rest % (NH + NKV);
    int s = rest / (NH + NKV);

    float* x;
    if (head < NH) x = q + (size_t)s * (NH * HD) + head * HD;
    else           x = k + (size_t)s * (NKV * HD) + (head - NH) * HD;

    float x0 = x[p], x1 = x[p + 32];
    const float* cp = cosb + (size_t)s * ROPE_D;
    const float* sp = sinb + (size_t)s * ROPE_D;
    float c0 = cp[p], s0 = sp[p];
    float c1 = cp[p + 32], s1 = sp[p + 32];
    x[p]      = x0 * c0 - x1 * s0;
    x[p + 32] = x1 * c1 + x0 * s1;
}

// ---------------------------------------------------------------------------
// Row softmax with causal mask + sink logit.
// Row (h, q): valid keys are 0..q. Sink contributes exp(sink-m) to the
// denominator only. Keys > q are written as 0.
// ---------------------------------------------------------------------------
__global__ void softmax_kernel(float* __restrict__ sc,
                               const float* __restrict__ sinks)
{
    int q = blockIdx.x, h = blockIdx.y;
    float* row = sc + ((size_t)h * SEQ + q) * SEQ;
    int len = q + 1;
    int tid = threadIdx.x;
    __shared__ float red[256];

    float m = -1e30f;
    for (int i = tid; i < len; i += 256) m = fmaxf(m, row[i]);
    red[tid] = m;
    __syncthreads();
    for (int s2 = 128; s2 > 0; s2 >>= 1) {
        if (tid < s2) red[tid] = fmaxf(red[tid], red[tid + s2]);
        __syncthreads();
    }
    float sink = sinks[h];
    m = fmaxf(red[0], sink);
    __syncthreads();

    float sum = 0.f;
    for (int i = tid; i < len; i += 256) {
        float e = expf(row[i] - m);
        row[i] = e;
        sum += e;
    }
    red[tid] = sum;
    __syncthreads();
    for (int s2 = 128; s2 > 0; s2 >>= 1) {
        if (tid < s2) red[tid] += red[tid + s2];
        __syncthreads();
    }
    float inv = 1.f / (red[0] + expf(sink - m));

    for (int i = tid; i < len; i += 256) row[i] *= inv;
    for (int i = len + tid; i < SEQ; i += 256) row[i] = 0.f;
}

// ---------------------------------------------------------------------------
extern "C" void kernel_launch(void* const* d_in, const int* in_sizes, int n_in,
                              void* d_out, int out_size)
{
    const float* X     = (const float*)d_in[0];  // (1, 2048, 4096)
    const float* cosb  = (const float*)d_in[1];  // (1,1,2048,64)
    const float* sinb  = (const float*)d_in[2];  // (1,1,2048,64)
    // d_in[3] = attention_mask (causal handled analytically)
    const float* Wq    = (const float*)d_in[4];  // (4096, 4096)
    const float* Wk    = (const float*)d_in[5];  // (4096, 1024)
    const float* Wv    = (const float*)d_in[6];  // (4096, 1024)
    const float* Wo    = (const float*)d_in[7];  // (4096, 4096)
    const float* sinks = (const float*)d_in[8];  // (32,)
    float* out = (float*)d_out;

    float *q, *k, *v, *sc, *at;
    cudaGetSymbolAddress((void**)&q,  g_q);
    cudaGetSymbolAddress((void**)&k,  g_k);
    cudaGetSymbolAddress((void**)&v,  g_v);
    cudaGetSymbolAddress((void**)&sc, g_sc);
    cudaGetSymbolAddress((void**)&at, g_at);

    const float scale = 0.08838834764831845f;  // 128^-0.5

    // 1-3. QKV projections
    sgemm_kernel<0,0><<<dim3(NH*HD/128, SEQ/128, 1), 256>>>(
        X, Wq, q, SEQ, NH*HD, HID, HID, NH*HD, NH*HD, 0, 0, 0, 1, 1.f);
    sgemm_kernel<0,0><<<dim3(NKV*HD/128, SEQ/128, 1), 256>>>(
        X, Wk, k, SEQ, NKV*HD, HID, HID, NKV*HD, NKV*HD, 0, 0, 0, 1, 1.f);
    sgemm_kernel<0,0><<<dim3(NKV*HD/128, SEQ/128, 1), 256>>>(
        X, Wv, v, SEQ, NKV*HD, HID, HID, NKV*HD, NKV*HD, 0, 0, 0, 1, 1.f);

    // 4. RoPE (in place on q, k)
    {
        int total = SEQ * (NH + NKV) * (ROPE_D / 2);
        rope_kernel<<<(total + 255) / 256, 256>>>(q, k, cosb, sinb);
    }

    // 5. scores[h] = scale * Q_h (2048x128) @ K_{h/4}^T (128x2048), causal skip
    sgemm_kernel<1,1><<<dim3(SEQ/128, SEQ/128, NH), 256>>>(
        q, k, sc, SEQ, SEQ, HD,
        NH*HD, NKV*HD, SEQ,
        /*sA=*/HD, /*sB=*/HD, /*sC=*/(long long)SEQ * SEQ, /*zdivB=*/NKV == 0 ? 1 : (NH / NKV),
        scale);

    // 6. causal softmax with sink
    softmax_kernel<<<dim3(SEQ, NH), 256>>>(sc, sinks);

    // 7. attn[h] = P_h (2048x2048) @ V_{h/4} (2048x128), K-limited by causal
    sgemm_kernel<0,1><<<dim3(HD/128, SEQ/128, NH), 256>>>(
        sc, v, at, SEQ, HD, SEQ,
        SEQ, NKV*HD, NH*HD,
        /*sA=*/(long long)SEQ * SEQ, /*sB=*/HD, /*sC=*/HD, /*zdivB=*/NH / NKV,
        1.f);

    // 8. output projection
    sgemm_kernel<0,0><<<dim3(HID/128, SEQ/128, 1), 256>>>(
        at, Wo, out, SEQ, HID, NH*HD, NH*HD, HID, HID, 0, 0, 0, 1, 1.f);
}

// round 4
// speedup vs baseline: 4.0123x; 4.0123x over previous
#include <cuda_runtime.h>
#include <cstdint>

#define SEQ 2048
#define HID 4096
#define NH  32
#define NKV 8
#define HD  128
#define ROPE_D 64

// Scratch (device globals -> no allocations)
__device__ float g_q [(size_t)SEQ * NH  * HD];   // 32 MB
__device__ float g_k [(size_t)SEQ * NKV * HD];   // 8 MB
__device__ float g_v [(size_t)SEQ * NKV * HD];   // 8 MB
__device__ float g_sc[(size_t)NH * SEQ * SEQ];   // 512 MB
__device__ float g_at[(size_t)SEQ * NH  * HD];   // 32 MB
// tf32-rounded copies of the read-only inputs
__device__ float g_X [(size_t)SEQ * HID];        // 32 MB
__device__ float g_Wq[(size_t)HID * NH  * HD];   // 64 MB
__device__ float g_Wk[(size_t)HID * NKV * HD];   // 16 MB
__device__ float g_Wv[(size_t)HID * NKV * HD];   // 16 MB
__device__ float g_Wo[(size_t)NH * HD * HID];    // 64 MB

// ---------------------------------------------------------------------------
// helpers
// ---------------------------------------------------------------------------
__device__ __forceinline__ uint32_t smem_u32(const void* p) {
    return (uint32_t)__cvta_generic_to_shared(p);
}
__device__ __forceinline__ void cp16(uint32_t s, const void* g) {
    asm volatile("cp.async.cg.shared.global [%0], [%1], 16;\n" :: "r"(s), "l"(g));
}
__device__ __forceinline__ float rnd_tf32(float x) {
    uint32_t u;
    asm("cvt.rna.tf32.f32 %0, %1;" : "=r"(u) : "f"(x));
    return __uint_as_float(u);
}

__global__ void round_copy(const float* __restrict__ src, float* __restrict__ dst, int n) {
    for (int i = blockIdx.x * blockDim.x + threadIdx.x; i < n; i += gridDim.x * blockDim.x)
        dst[i] = rnd_tf32(src[i]);
}

// ---------------------------------------------------------------------------
// tf32 tensor-core GEMM: C[M,N] = alpha * A[M,K] * op(B)
//   TRANSB=1: B is [N,K] row-major (B^T applied). TRANSB=0: B is [K,N].
// Tiles: 128x128x32, 8 warps (2m x 4n), warp tile 64x32, mma m16n8k8 tf32.
// 3-stage cp.async pipeline. All inputs must already be tf32-rounded values.
// CAUSAL&&TRANSB: skip tiles with bn>bm. CAUSAL&&!TRANSB: K limited to (bm+1)*128.
// ---------------------------------------------------------------------------
#define STAGEF 8448            // floats per stage: A 128*32 + B 32*136 (padded)
#define SMEM_BYTES (3 * STAGEF * 4)

template<int TRANSB, int CAUSAL, int ROUND_OUT>
__global__ __launch_bounds__(256)
void mma_gemm(const float* __restrict__ A, const float* __restrict__ B,
              float* __restrict__ C, int M, int N, int K,
              int lda, int ldb, int ldc,
              long long sA, long long sB, long long sC, int zdivB,
              float alpha)
{
    int bm = blockIdx.y, bn = blockIdx.x, bz = blockIdx.z;
    if (CAUSAL && TRANSB && bn > bm) return;

    A += (long long)bz * sA;
    B += (long long)(bz / zdivB) * sB;
    C += (long long)bz * sC;

    int Kend = K;
    if (CAUSAL && !TRANSB) {
        int lim = (bm + 1) * 128;
        Kend = (K < lim) ? K : lim;
    }
    int niter = Kend >> 5;

    extern __shared__ float smem[];
    int tid = threadIdx.x;
    int lane = tid & 31, warp = tid >> 5;
    int wm = warp & 1, wn = warp >> 1;

    const float* Ag = A + (size_t)(bm * 128) * lda;
    const float* Bg1 = B + (size_t)(bn * 128) * ldb;   // TRANSB=1 base
    const float* Bg0 = B + bn * 128;                   // TRANSB=0 base

    auto issue_tiles = [&](int stage, int k0) {
        float* As = smem + stage * STAGEF;
        float* Bs = As + 4096;
#pragma unroll
        for (int i = 0; i < 4; i++) {
            int ch = tid + i * 256;
            int r = ch >> 3, c = ch & 7;
            cp16(smem_u32(As + r * 32 + ((c ^ (r & 7)) << 2)),
                 Ag + (size_t)r * lda + k0 + c * 4);
        }
        if (TRANSB) {
#pragma unroll
            for (int i = 0; i < 4; i++) {
                int ch = tid + i * 256;
                int r = ch >> 3, c = ch & 7;
                cp16(smem_u32(Bs + r * 32 + ((c ^ (r & 7)) << 2)),
                     Bg1 + (size_t)r * ldb + k0 + c * 4);
            }
        } else {
#pragma unroll
            for (int i = 0; i < 4; i++) {
                int ch = tid + i * 256;
                int r = ch >> 5, c = ch & 31;
                cp16(smem_u32(Bs + r * 136 + c * 4),
                     Bg0 + (size_t)(k0 + r) * ldb + c * 4);
            }
        }
    };

    float acc[4][4][4];
#pragma unroll
    for (int i = 0; i < 4; i++)
#pragma unroll
        for (int j = 0; j < 4; j++)
#pragma unroll
            for (int t = 0; t < 4; t++) acc[i][j][t] = 0.f;

    // pipeline prologue: stages 0,1
    issue_tiles(0, 0);
    asm volatile("cp.async.commit_group;");
    if (niter > 1) issue_tiles(1, 32);
    asm volatile("cp.async.commit_group;");
    asm volatile("cp.async.wait_group 1;");
    __syncthreads();

    for (int it = 0; it < niter; it++) {
        int cur = it % 3;
        int nxt = it + 2;
        if (nxt < niter) issue_tiles(nxt % 3, nxt * 32);
        asm volatile("cp.async.commit_group;");

        const float* As = smem + cur * STAGEF;
        const float* Bsm = As + 4096;
#pragma unroll
        for (int kk = 0; kk < 4; kk++) {
            uint32_t a[4][4];
#pragma unroll
            for (int im = 0; im < 4; im++) {
                int r = wm * 64 + im * 16 + ((lane >> 3) & 1) * 8 + (lane & 7);
                int c = kk * 2 + (lane >> 4);
                uint32_t addr = smem_u32(As + r * 32 + ((c ^ (r & 7)) << 2));
                asm volatile("ldmatrix.sync.aligned.m8n8.x4.shared.b16 {%0,%1,%2,%3}, [%4];"
                             : "=r"(a[im][0]), "=r"(a[im][1]), "=r"(a[im][2]), "=r"(a[im][3])
                             : "r"(addr));
            }
            uint32_t b[4][2];
            if (TRANSB) {
#pragma unroll
                for (int jp = 0; jp < 2; jp++) {
                    int n = wn * 32 + jp * 16 + (lane >> 4) * 8 + (lane & 7);
                    int c = kk * 2 + ((lane >> 3) & 1);
                    uint32_t addr = smem_u32(Bsm + n * 32 + ((c ^ (n & 7)) << 2));
                    asm volatile("ldmatrix.sync.aligned.m8n8.x4.shared.b16 {%0,%1,%2,%3}, [%4];"
                                 : "=r"(b[2 * jp][0]), "=r"(b[2 * jp][1]),
                                   "=r"(b[2 * jp + 1][0]), "=r"(b[2 * jp + 1][1])
                                 : "r"(addr));
                }
            } else {
                int gid = lane >> 2, tig = lane & 3;
#pragma unroll
                for (int jn = 0; jn < 4; jn++) {
                    int n0 = wn * 32 + jn * 8 + gid;
                    b[jn][0] = __float_as_uint(Bsm[(kk * 8 + tig) * 136 + n0]);
                    b[jn][1] = __float_as_uint(Bsm[(kk * 8 + tig + 4) * 136 + n0]);
                }
            }
#pragma unroll
            for (int im = 0; im < 4; im++)
#pragma unroll
                for (int jn = 0; jn < 4; jn++) {
                    asm volatile(
                        "mma.sync.aligned.m16n8k8.row.col.f32.tf32.tf32.f32 "
                        "{%0,%1,%2,%3}, {%4,%5,%6,%7}, {%8,%9}, {%0,%1,%2,%3};"
                        : "+f"(acc[im][jn][0]), "+f"(acc[im][jn][1]),
                          "+f"(acc[im][jn][2]), "+f"(acc[im][jn][3])
                        : "r"(a[im][0]), "r"(a[im][1]), "r"(a[im][2]), "r"(a[im][3]),
                          "r"(b[jn][0]), "r"(b[jn][1]));
                }
        }
        asm volatile("cp.async.wait_group 1;");
        __syncthreads();
    }

    // epilogue
    int gid = lane >> 2, tig = lane & 3;
#pragma unroll
    for (int im = 0; im < 4; im++) {
        int row0 = bm * 128 + wm * 64 + im * 16 + gid;
#pragma unroll
        for (int jn = 0; jn < 4; jn++) {
            int col = bn * 128 + wn * 32 + jn * 8 + tig * 2;
            float v0 = alpha * acc[im][jn][0];
            float v1 = alpha * acc[im][jn][1];
            float v2 = alpha * acc[im][jn][2];
            float v3 = alpha * acc[im][jn][3];
            if (ROUND_OUT) {
                v0 = rnd_tf32(v0); v1 = rnd_tf32(v1);
                v2 = rnd_tf32(v2); v3 = rnd_tf32(v3);
            }
            *(float2*)&C[(size_t)row0 * ldc + col] = make_float2(v0, v1);
            *(float2*)&C[(size_t)(row0 + 8) * ldc + col] = make_float2(v2, v3);
        }
    }
}

// ---------------------------------------------------------------------------
// RoPE on Q (32 heads) and K (8 heads), first 64 dims. Outputs tf32-rounded.
// ---------------------------------------------------------------------------
__global__ void rope_kernel(float* __restrict__ q, float* __restrict__ k,
                            const float* __restrict__ cosb,
                            const float* __restrict__ sinb)
{
    int idx = blockIdx.x * blockDim.x + threadIdx.x;
    const int total = SEQ * (NH + NKV) * (ROPE_D / 2);
    if (idx >= total) return;
    int p = idx & 31;
    int rest = idx >> 5;
    int head = rest % (NH + NKV);
    int s = rest / (NH + NKV);

    float* x;
    if (head < NH) x = q + (size_t)s * (NH * HD) + head * HD;
    else           x = k + (size_t)s * (NKV * HD) + (head - NH) * HD;

    float x0 = x[p], x1 = x[p + 32];
    const float* cp = cosb + (size_t)s * ROPE_D;
    const float* sp = sinb + (size_t)s * ROPE_D;
    float c0 = cp[p], s0 = sp[p];
    float c1 = cp[p + 32], s1 = sp[p + 32];
    x[p]      = rnd_tf32(x0 * c0 - x1 * s0);
    x[p + 32] = rnd_tf32(x1 * c1 + x0 * s1);
}

// ---------------------------------------------------------------------------
// Row softmax with causal mask + sink logit. P written tf32-rounded.
// ---------------------------------------------------------------------------
__global__ void softmax_kernel(float* __restrict__ sc,
                               const float* __restrict__ sinks)
{
    int q = blockIdx.x, h = blockIdx.y;
    float* row = sc + ((size_t)h * SEQ + q) * SEQ;
    int len = q + 1;
    int tid = threadIdx.x;
    __shared__ float red[256];

    float m = -1e30f;
    for (int i = tid; i < len; i += 256) m = fmaxf(m, row[i]);
    red[tid] = m;
    __syncthreads();
    for (int s2 = 128; s2 > 0; s2 >>= 1) {
        if (tid < s2) red[tid] = fmaxf(red[tid], red[tid + s2]);
        __syncthreads();
    }
    float sink = sinks[h];
    m = fmaxf(red[0], sink);
    __syncthreads();

    float sum = 0.f;
    for (int i = tid; i < len; i += 256) {
        float e = expf(row[i] - m);
        row[i] = e;
        sum += e;
    }
    red[tid] = sum;
    __syncthreads();
    for (int s2 = 128; s2 > 0; s2 >>= 1) {
        if (tid < s2) red[tid] += red[tid + s2];
        __syncthreads();
    }
    float inv = 1.f / (red[0] + expf(sink - m));

    for (int i = tid; i < len; i += 256) row[i] = rnd_tf32(row[i] * inv);
    for (int i = len + tid; i < SEQ; i += 256) row[i] = 0.f;
}

// ---------------------------------------------------------------------------
extern "C" void kernel_launch(void* const* d_in, const int* in_sizes, int n_in,
                              void* d_out, int out_size)
{
    const float* X_in  = (const float*)d_in[0];
    const float* cosb  = (const float*)d_in[1];
    const float* sinb  = (const float*)d_in[2];
    const float* Wq_in = (const float*)d_in[4];
    const float* Wk_in = (const float*)d_in[5];
    const float* Wv_in = (const float*)d_in[6];
    const float* Wo_in = (const float*)d_in[7];
    const float* sinks = (const float*)d_in[8];
    float* out = (float*)d_out;

    float *q, *k, *v, *sc, *at, *X, *Wq, *Wk, *Wv, *Wo;
    cudaGetSymbolAddress((void**)&q,  g_q);
    cudaGetSymbolAddress((void**)&k,  g_k);
    cudaGetSymbolAddress((void**)&v,  g_v);
    cudaGetSymbolAddress((void**)&sc, g_sc);
    cudaGetSymbolAddress((void**)&at, g_at);
    cudaGetSymbolAddress((void**)&X,  g_X);
    cudaGetSymbolAddress((void**)&Wq, g_Wq);
    cudaGetSymbolAddress((void**)&Wk, g_Wk);
    cudaGetSymbolAddress((void**)&Wv, g_Wv);
    cudaGetSymbolAddress((void**)&Wo, g_Wo);

    cudaFuncSetAttribute((const void*)mma_gemm<0,0,1>, cudaFuncAttributeMaxDynamicSharedMemorySize, SMEM_BYTES);
    cudaFuncSetAttribute((const void*)mma_gemm<0,0,0>, cudaFuncAttributeMaxDynamicSharedMemorySize, SMEM_BYTES);
    cudaFuncSetAttribute((const void*)mma_gemm<1,1,0>, cudaFuncAttributeMaxDynamicSharedMemorySize, SMEM_BYTES);
    cudaFuncSetAttribute((const void*)mma_gemm<0,1,1>, cudaFuncAttributeMaxDynamicSharedMemorySize, SMEM_BYTES);

    const float scale = 0.08838834764831845f;  // 128^-0.5

    // 0. tf32-round the read-only inputs (rne; avoids biased HW truncation)
    round_copy<<<4096, 256>>>(X_in,  X,  SEQ * HID);
    round_copy<<<8192, 256>>>(Wq_in, Wq, HID * NH * HD);
    round_copy<<<4096, 256>>>(Wk_in, Wk, HID * NKV * HD);
    round_copy<<<4096, 256>>>(Wv_in, Wv, HID * NKV * HD);
    round_copy<<<8192, 256>>>(Wo_in, Wo, NH * HD * HID);

    // 1-3. QKV projections (outputs rounded)
    mma_gemm<0,0,1><<<dim3(NH*HD/128, SEQ/128, 1), 256, SMEM_BYTES>>>(
        X, Wq, q, SEQ, NH*HD, HID, HID, NH*HD, NH*HD, 0, 0, 0, 1, 1.f);
    mma_gemm<0,0,1><<<dim3(NKV*HD/128, SEQ/128, 1), 256, SMEM_BYTES>>>(
        X, Wk, k, SEQ, NKV*HD, HID, HID, NKV*HD, NKV*HD, 0, 0, 0, 1, 1.f);
    mma_gemm<0,0,1><<<dim3(NKV*HD/128, SEQ/128, 1), 256, SMEM_BYTES>>>(
        X, Wv, v, SEQ, NKV*HD, HID, HID, NKV*HD, NKV*HD, 0, 0, 0, 1, 1.f);

    // 4. RoPE (in place; rounded)
    {
        int total = SEQ * (NH + NKV) * (ROPE_D / 2);
        rope_kernel<<<(total + 255) / 256, 256>>>(q, k, cosb, sinb);
    }

    // 5. scores = scale * Q @ K^T (causal tile skip)
    mma_gemm<1,1,0><<<dim3(SEQ/128, SEQ/128, NH), 256, SMEM_BYTES>>>(
        q, k, sc, SEQ, SEQ, HD,
        NH*HD, NKV*HD, SEQ,
        (long long)HD, (long long)HD, (long long)SEQ * SEQ, NH / NKV,
        scale);

    // 6. causal softmax with sink (P rounded)
    softmax_kernel<<<dim3(SEQ, NH), 256>>>(sc, sinks);

    // 7. attn = P @ V (K-limited by causal; rounded)
    mma_gemm<0,1,1><<<dim3(HD/128, SEQ/128, NH), 256, SMEM_BYTES>>>(
        sc, v, at, SEQ, HD, SEQ,
        SEQ, NKV*HD, NH*HD,
        (long long)SEQ * SEQ, (long long)HD, (long long)HD, NH / NKV,
        1.f);

    // 8. output projection (fp32 out)
    mma_gemm<0,0,0><<<dim3(HID/128, SEQ/128, 1), 256, SMEM_BYTES>>>(
        at, Wo, out, SEQ, HID, NH*HD, NH*HD, HID, HID, 0, 0, 0, 1, 1.f);
}